// round 2
// baseline (speedup 1.0000x reference)
#include <cuda_runtime.h>
#include <cstddef>

#define Bn 16
#define Cn 320
#define Hn 64
#define Wn 64
#define HWn 4096          // Hn*Wn
#define PIXn (Bn*HWn)     // 65536 pixels

// Scratch (allocation-free requirement -> __device__ globals)
__device__ __align__(16) float g_em[PIXn];        // edge_map mean   [B,H,W]
__device__ __align__(16) float g_h [PIXn * 16];   // conv1 output    [B,H,W,16]
__device__ __align__(16) float g_w0[PIXn];        // softmax weight0 [B,H,W]

// ---------------------------------------------------------------------------
// k1: edge_map = mean over C of edge_guidance.  One thread per (b,h,w) pixel.
// Consecutive threads -> consecutive hw -> perfectly coalesced 128B per warp
// per channel step. Unroll 8 for MLP.
// ---------------------------------------------------------------------------
__global__ void k_mean(const float* __restrict__ eg) {
    int p = blockIdx.x * blockDim.x + threadIdx.x;   // 0..65535
    int b = p >> 12;
    int hw = p & 4095;
    const float* ptr = eg + (size_t)b * Cn * HWn + hw;
    float s = 0.f;
#pragma unroll 8
    for (int c = 0; c < Cn; ++c)
        s += __ldg(ptr + (size_t)c * HWn);
    g_em[p] = s * (1.0f / (float)Cn);
}

// ---------------------------------------------------------------------------
// k2: h = relu(conv3x3(edge_map, w1) + b1), 1 -> 16 channels, SAME (zero) pad.
// One thread per pixel; output layout [B,H,W,16] so each thread writes 64
// contiguous bytes (4x float4).
// ---------------------------------------------------------------------------
__global__ void k_conv1(const float* __restrict__ w1, const float* __restrict__ b1) {
    int p = blockIdx.x * blockDim.x + threadIdx.x;
    int xx = p & 63;
    int yy = (p >> 6) & 63;
    int b  = p >> 12;

    float patch[3][3];
#pragma unroll
    for (int dy = -1; dy <= 1; ++dy)
#pragma unroll
        for (int dx = -1; dx <= 1; ++dx) {
            int py = yy + dy, px = xx + dx;
            patch[dy + 1][dx + 1] =
                (py >= 0 && py < Hn && px >= 0 && px < Wn)
                    ? g_em[b * HWn + py * Wn + px] : 0.f;
        }

    float acc[16];
#pragma unroll
    for (int c = 0; c < 16; ++c) {
        float a = __ldg(b1 + c);
#pragma unroll
        for (int ky = 0; ky < 3; ++ky)
#pragma unroll
            for (int kx = 0; kx < 3; ++kx)
                a = fmaf(__ldg(w1 + c * 9 + ky * 3 + kx), patch[ky][kx], a);
        acc[c] = fmaxf(a, 0.f);
    }

    float4* o = (float4*)(g_h + (size_t)p * 16);
    o[0] = make_float4(acc[0],  acc[1],  acc[2],  acc[3]);
    o[1] = make_float4(acc[4],  acc[5],  acc[6],  acc[7]);
    o[2] = make_float4(acc[8],  acc[9],  acc[10], acc[11]);
    o[3] = make_float4(acc[12], acc[13], acc[14], acc[15]);
}

// ---------------------------------------------------------------------------
// k3: dir_logits = conv3x3(h, w2) + b2 (16 -> 2), then 2-class softmax:
// w0 = sigmoid(l0 - l1). One thread per pixel; w2 staged in smem.
// SAME pad on h: out-of-bounds positions contribute zero.
// ---------------------------------------------------------------------------
__global__ void k_conv2(const float* __restrict__ w2, const float* __restrict__ b2) {
    __shared__ float sw2[288];
    __shared__ float sb2[2];
    for (int i = threadIdx.x; i < 288; i += blockDim.x) sw2[i] = w2[i];
    if (threadIdx.x < 2) sb2[threadIdx.x] = b2[threadIdx.x];
    __syncthreads();

    int p = blockIdx.x * blockDim.x + threadIdx.x;
    int xx = p & 63;
    int yy = (p >> 6) & 63;
    int b  = p >> 12;

    float l0 = sb2[0], l1 = sb2[1];
#pragma unroll
    for (int ky = 0; ky < 3; ++ky) {
#pragma unroll
        for (int kx = 0; kx < 3; ++kx) {
            int py = yy + ky - 1, px = xx + kx - 1;
            if (py < 0 || py >= Hn || px < 0 || px >= Wn) continue;
            const float4* hp =
                (const float4*)(g_h + (size_t)(b * HWn + py * Wn + px) * 16);
            int koff = ky * 3 + kx;
#pragma unroll
            for (int q = 0; q < 4; ++q) {
                float4 hv = hp[q];
                int c0 = q * 4;
                l0 = fmaf(sw2[(c0 + 0) * 9 + koff], hv.x, l0);
                l0 = fmaf(sw2[(c0 + 1) * 9 + koff], hv.y, l0);
                l0 = fmaf(sw2[(c0 + 2) * 9 + koff], hv.z, l0);
                l0 = fmaf(sw2[(c0 + 3) * 9 + koff], hv.w, l0);
                l1 = fmaf(sw2[144 + (c0 + 0) * 9 + koff], hv.x, l1);
                l1 = fmaf(sw2[144 + (c0 + 1) * 9 + koff], hv.y, l1);
                l1 = fmaf(sw2[144 + (c0 + 2) * 9 + koff], hv.z, l1);
                l1 = fmaf(sw2[144 + (c0 + 3) * 9 + koff], hv.w, l1);
            }
        }
    }
    // softmax over 2 classes: w0 = exp(l0)/(exp(l0)+exp(l1)) = sigmoid(l0-l1)
    g_w0[p] = 1.0f / (1.0f + expf(l1 - l0));
}

// ---------------------------------------------------------------------------
// k4: out = w0 * x[h - sh[g], w] + (1-w0) * x[h, w - sw[g]]  (zero fill OOB)
// Rolling a PAD=2 zero-padded tensor by |s|<=2 then cropping == zero-filled
// shift, no wraparound. One thread per 4 consecutive w (float4 on the
// h-shifted read and the store; 4 scalar loads for the misaligned w-shift,
// which hit L1/L2 lines fetched by neighboring threads).
// ---------------------------------------------------------------------------
__global__ void k_shift(const float* __restrict__ x,
                        const int* __restrict__ shv,
                        const int* __restrict__ swv,
                        float* __restrict__ out) {
    int idx = blockIdx.x * blockDim.x + threadIdx.x;  // < B*C*H*(W/4)
    int wq = idx & 15;
    int h  = (idx >> 4) & 63;
    int t  = idx >> 10;
    int b  = t / Cn;
    int c  = t - b * Cn;
    int g  = c >> 6;                 // C/G = 320/5 = 64 channels per group
    int sh = __ldg(shv + g);
    int sw = __ldg(swv + g);

    float4 wgt = *(const float4*)(g_w0 + b * HWn + h * Wn + wq * 4);
    size_t base = (size_t)(b * Cn + c) * HWn;

    int hh = h - sh;
    float4 hv = make_float4(0.f, 0.f, 0.f, 0.f);
    if ((unsigned)hh < (unsigned)Hn)
        hv = *(const float4*)(x + base + hh * Wn + wq * 4);

    float wv[4];
#pragma unroll
    for (int i = 0; i < 4; ++i) {
        int ww = wq * 4 + i - sw;
        wv[i] = ((unsigned)ww < (unsigned)Wn)
                    ? __ldg(x + base + h * Wn + ww) : 0.f;
    }

    float4 o;
    o.x = wgt.x * hv.x + (1.f - wgt.x) * wv[0];
    o.y = wgt.y * hv.y + (1.f - wgt.y) * wv[1];
    o.z = wgt.z * hv.z + (1.f - wgt.z) * wv[2];
    o.w = wgt.w * hv.w + (1.f - wgt.w) * wv[3];
    *(float4*)(out + base + h * Wn + wq * 4) = o;
}

// ---------------------------------------------------------------------------
extern "C" void kernel_launch(void* const* d_in, const int* in_sizes, int n_in,
                              void* d_out, int out_size) {
    const float* x   = (const float*)d_in[0];
    const float* eg  = (const float*)d_in[1];
    const float* w1  = (const float*)d_in[2];
    const float* b1  = (const float*)d_in[3];
    const float* w2  = (const float*)d_in[4];
    const float* b2  = (const float*)d_in[5];
    const int*   shv = (const int*)d_in[6];
    const int*   swv = (const int*)d_in[7];
    float* out = (float*)d_out;

    k_mean <<<512, 128>>>(eg);           // 65536 threads
    k_conv1<<<256, 256>>>(w1, b1);       // 65536 threads
    k_conv2<<<256, 256>>>(w2, b2);       // 65536 threads
    k_shift<<<20480, 256>>>(x, shv, swv, out);  // 5,242,880 threads
}

// round 3
// speedup vs baseline: 1.1380x; 1.1380x over previous
#include <cuda_runtime.h>
#include <cstddef>

#define Bn 16
#define Cn 320
#define Hn 64
#define Wn 64
#define HWn 4096          // Hn*Wn
#define PIXn (Bn*HWn)     // 65536 pixels
#define SPLIT 8
#define CPS (Cn / SPLIT)  // 40 channels per split

// Scratch (allocation-free requirement -> __device__ globals)
__device__ __align__(16) float g_part[SPLIT * PIXn]; // partial channel sums
__device__ __align__(16) float g_em[PIXn];           // edge_map mean   [B,H,W]
__device__ __align__(16) float g_h [PIXn * 16];      // conv1 out [B,H,W,16]
__device__ __align__(16) float g_w0[PIXn];           // softmax weight0 [B,H,W]

// ---------------------------------------------------------------------------
// k1a: partial channel sums, 8-way split over C for 8x memory parallelism.
// idx = s*PIXn + p ; warp = 32 consecutive p, same s -> coalesced 128B.
// ---------------------------------------------------------------------------
__global__ void k_mean_part(const float* __restrict__ eg) {
    int idx = blockIdx.x * blockDim.x + threadIdx.x;  // < SPLIT*PIXn
    int p = idx & (PIXn - 1);
    int s = idx >> 16;
    int b = p >> 12;
    int hw = p & 4095;
    const float* ptr = eg + (size_t)b * Cn * HWn + (size_t)s * CPS * HWn + hw;
    float a0 = 0.f, a1 = 0.f, a2 = 0.f, a3 = 0.f;
#pragma unroll
    for (int c = 0; c < CPS; c += 4) {
        a0 += __ldg(ptr + (size_t)(c + 0) * HWn);
        a1 += __ldg(ptr + (size_t)(c + 1) * HWn);
        a2 += __ldg(ptr + (size_t)(c + 2) * HWn);
        a3 += __ldg(ptr + (size_t)(c + 3) * HWn);
    }
    g_part[idx] = (a0 + a1) + (a2 + a3);
}

// k1b: reduce the 8 partials (2MB, L2-resident) -> mean
__global__ void k_mean_sum(int dummy) {
    int p = blockIdx.x * blockDim.x + threadIdx.x;
    float s = 0.f;
#pragma unroll
    for (int k = 0; k < SPLIT; ++k)
        s += g_part[k * PIXn + p];
    g_em[p] = s * (1.0f / (float)Cn);
}

// ---------------------------------------------------------------------------
// k2: h = relu(conv3x3(edge_map, w1) + b1), 1 -> 16 ch, SAME pad.
// Output layout [B,H,W,16]: each thread writes 64 contiguous bytes.
// ---------------------------------------------------------------------------
__global__ void k_conv1(const float* __restrict__ w1, const float* __restrict__ b1) {
    int p = blockIdx.x * blockDim.x + threadIdx.x;
    int xx = p & 63;
    int yy = (p >> 6) & 63;
    int b  = p >> 12;

    float patch[3][3];
#pragma unroll
    for (int dy = -1; dy <= 1; ++dy)
#pragma unroll
        for (int dx = -1; dx <= 1; ++dx) {
            int py = yy + dy, px = xx + dx;
            patch[dy + 1][dx + 1] =
                (py >= 0 && py < Hn && px >= 0 && px < Wn)
                    ? g_em[b * HWn + py * Wn + px] : 0.f;
        }

    float acc[16];
#pragma unroll
    for (int c = 0; c < 16; ++c) {
        float a = __ldg(b1 + c);
#pragma unroll
        for (int ky = 0; ky < 3; ++ky)
#pragma unroll
            for (int kx = 0; kx < 3; ++kx)
                a = fmaf(__ldg(w1 + c * 9 + ky * 3 + kx), patch[ky][kx], a);
        acc[c] = fmaxf(a, 0.f);
    }

    float4* o = (float4*)(g_h + (size_t)p * 16);
    o[0] = make_float4(acc[0],  acc[1],  acc[2],  acc[3]);
    o[1] = make_float4(acc[4],  acc[5],  acc[6],  acc[7]);
    o[2] = make_float4(acc[8],  acc[9],  acc[10], acc[11]);
    o[3] = make_float4(acc[12], acc[13], acc[14], acc[15]);
}

// ---------------------------------------------------------------------------
// k3: dir_logits = conv3x3(h, w2) + b2 (16 -> 2), softmax over 2 classes:
// w0 = sigmoid(l0 - l1).
// ---------------------------------------------------------------------------
__global__ void k_conv2(const float* __restrict__ w2, const float* __restrict__ b2) {
    __shared__ float sw2[288];
    __shared__ float sb2[2];
    for (int i = threadIdx.x; i < 288; i += blockDim.x) sw2[i] = w2[i];
    if (threadIdx.x < 2) sb2[threadIdx.x] = b2[threadIdx.x];
    __syncthreads();

    int p = blockIdx.x * blockDim.x + threadIdx.x;
    int xx = p & 63;
    int yy = (p >> 6) & 63;
    int b  = p >> 12;

    float l0 = sb2[0], l1 = sb2[1];
#pragma unroll
    for (int ky = 0; ky < 3; ++ky) {
#pragma unroll
        for (int kx = 0; kx < 3; ++kx) {
            int py = yy + ky - 1, px = xx + kx - 1;
            if (py < 0 || py >= Hn || px < 0 || px >= Wn) continue;
            const float4* hp =
                (const float4*)(g_h + (size_t)(b * HWn + py * Wn + px) * 16);
            int koff = ky * 3 + kx;
#pragma unroll
            for (int q = 0; q < 4; ++q) {
                float4 hv = hp[q];
                int c0 = q * 4;
                l0 = fmaf(sw2[(c0 + 0) * 9 + koff], hv.x, l0);
                l0 = fmaf(sw2[(c0 + 1) * 9 + koff], hv.y, l0);
                l0 = fmaf(sw2[(c0 + 2) * 9 + koff], hv.z, l0);
                l0 = fmaf(sw2[(c0 + 3) * 9 + koff], hv.w, l0);
                l1 = fmaf(sw2[144 + (c0 + 0) * 9 + koff], hv.x, l1);
                l1 = fmaf(sw2[144 + (c0 + 1) * 9 + koff], hv.y, l1);
                l1 = fmaf(sw2[144 + (c0 + 2) * 9 + koff], hv.z, l1);
                l1 = fmaf(sw2[144 + (c0 + 3) * 9 + koff], hv.w, l1);
            }
        }
    }
    g_w0[p] = 1.0f / (1.0f + expf(l1 - l0));
}

// ---------------------------------------------------------------------------
// k4: out = w0 * x[h - sh[g], w] + (1-w0) * x[h, w - sw[g]]  (zero fill OOB)
// A warp holds 2 full rows (16 lanes x float4 each). |sw| <= 2 and sw is
// warp-uniform, so the w-shifted values come from the same/adjacent lane via
// __shfl (<=2 shuffles) instead of 4 scalar LDGs. Row boundary == zero-fill
// boundary (lane L==0 / L==15).
// ---------------------------------------------------------------------------
__global__ void k_shift(const float* __restrict__ x,
                        const int* __restrict__ shv,
                        const int* __restrict__ swv,
                        float* __restrict__ out) {
    int idx = blockIdx.x * blockDim.x + threadIdx.x;  // < B*C*H*(W/4)
    int wq = idx & 15;
    int h  = (idx >> 4) & 63;
    int t  = idx >> 10;           // b*Cn + c ; uniform across warp
    int b  = t / Cn;
    int c  = t - b * Cn;
    int g  = c >> 6;              // 64 channels per group
    int sh = __ldg(shv + g);
    int sw = __ldg(swv + g);
    int L  = threadIdx.x & 15;    // position within row

    size_t base = (size_t)t * HWn;

    // aligned row quad (shuffle source / sw==0 value)
    const float4 A = *(const float4*)(x + base + h * Wn + wq * 4);

    // h-shifted quad (vectorized; row +-2 -> L2 hit)
    int hh = h - sh;
    float4 hv = make_float4(0.f, 0.f, 0.f, 0.f);
    if ((unsigned)hh < (unsigned)Hn)
        hv = *(const float4*)(x + base + hh * Wn + wq * 4);

    // w-shifted quad via shuffle (warp-uniform branch)
    float4 wv;
    if (sw == 0) {
        wv = A;
    } else if (sw == 1) {
        float lw = __shfl_up_sync(0xffffffffu, A.w, 1);
        wv = make_float4(L > 0 ? lw : 0.f, A.x, A.y, A.z);
    } else if (sw == 2) {
        float lz = __shfl_up_sync(0xffffffffu, A.z, 1);
        float lw = __shfl_up_sync(0xffffffffu, A.w, 1);
        wv = make_float4(L > 0 ? lz : 0.f, L > 0 ? lw : 0.f, A.x, A.y);
    } else if (sw == -1) {
        float rx = __shfl_down_sync(0xffffffffu, A.x, 1);
        wv = make_float4(A.y, A.z, A.w, L < 15 ? rx : 0.f);
    } else { // sw == -2
        float rx = __shfl_down_sync(0xffffffffu, A.x, 1);
        float ry = __shfl_down_sync(0xffffffffu, A.y, 1);
        wv = make_float4(A.z, A.w, L < 15 ? rx : 0.f, L < 15 ? ry : 0.f);
    }

    float4 wgt = *(const float4*)(g_w0 + b * HWn + h * Wn + wq * 4);

    float4 o;
    o.x = wgt.x * hv.x + (1.f - wgt.x) * wv.x;
    o.y = wgt.y * hv.y + (1.f - wgt.y) * wv.y;
    o.z = wgt.z * hv.z + (1.f - wgt.z) * wv.z;
    o.w = wgt.w * hv.w + (1.f - wgt.w) * wv.w;
    *(float4*)(out + base + h * Wn + wq * 4) = o;
}

// ---------------------------------------------------------------------------
extern "C" void kernel_launch(void* const* d_in, const int* in_sizes, int n_in,
                              void* d_out, int out_size) {
    const float* x   = (const float*)d_in[0];
    const float* eg  = (const float*)d_in[1];
    const float* w1  = (const float*)d_in[2];
    const float* b1  = (const float*)d_in[3];
    const float* w2  = (const float*)d_in[4];
    const float* b2  = (const float*)d_in[5];
    const int*   shv = (const int*)d_in[6];
    const int*   swv = (const int*)d_in[7];
    float* out = (float*)d_out;

    k_mean_part<<<2048, 256>>>(eg);       // 524288 threads
    k_mean_sum <<<256, 256>>>(0);         // 65536 threads
    k_conv1    <<<256, 256>>>(w1, b1);    // 65536 threads
    k_conv2    <<<256, 256>>>(w2, b2);    // 65536 threads
    k_shift    <<<20480, 256>>>(x, shv, swv, out);  // 5,242,880 threads
}

// round 4
// speedup vs baseline: 1.2484x; 1.0970x over previous
#include <cuda_runtime.h>
#include <cstddef>

#define Bn 16
#define Cn 320
#define Hn 64
#define Wn 64
#define HWn 4096          // Hn*Wn
#define PIXn (Bn*HWn)     // 65536 pixels
#define SPLIT 8
#define CPS (Cn / SPLIT)  // 40 channels per split

// Scratch (allocation-free requirement -> __device__ globals)
__device__ __align__(16) float g_part[SPLIT * PIXn]; // partial channel sums
__device__ __align__(16) float g_w0[PIXn];           // softmax weight0 [B,H,W]

// ---------------------------------------------------------------------------
// k1: partial channel sums, 8-way split over C for 8x memory parallelism.
// idx = s*PIXn + p ; warp = 32 consecutive p, same s -> coalesced 128B.
// ---------------------------------------------------------------------------
__global__ void k_mean_part(const float* __restrict__ eg) {
    int idx = blockIdx.x * blockDim.x + threadIdx.x;  // < SPLIT*PIXn
    int p = idx & (PIXn - 1);
    int s = idx >> 16;
    int b = p >> 12;
    int hw = p & 4095;
    const float* ptr = eg + (size_t)b * Cn * HWn + (size_t)s * CPS * HWn + hw;
    float a0 = 0.f, a1 = 0.f, a2 = 0.f, a3 = 0.f;
#pragma unroll
    for (int c = 0; c < CPS; c += 4) {
        a0 += __ldg(ptr + (size_t)(c + 0) * HWn);
        a1 += __ldg(ptr + (size_t)(c + 1) * HWn);
        a2 += __ldg(ptr + (size_t)(c + 2) * HWn);
        a3 += __ldg(ptr + (size_t)(c + 3) * HWn);
    }
    g_part[idx] = (a0 + a1) + (a2 + a3);
}

// ---------------------------------------------------------------------------
// k_gate: fused  mean-finalize -> conv1(1->16)+relu -> conv2(16->2) -> sigmoid
// One block per 16x16 output tile (256 blocks, 256 threads).
//   stage 1: em tile + 2-halo (20x20) in smem, summing g_part's 8 partials
//   stage 2: conv1 at 18x18 h-positions -> smem, layout [c][pos] (conflict-free
//            stage-3 reads); h outside the image is zeroed (conv2 SAME pad)
//   stage 3: conv2 + 2-class softmax (sigmoid of logit diff) -> g_w0
// No global intermediates besides g_part/g_w0; g_h/g_em tensors eliminated.
// ---------------------------------------------------------------------------
#define TS 16
#define EMD 20            // em tile dim (TS + 2*2 halo)
#define HD 18             // h tile dim  (TS + 2*1 halo)
#define HPOS (HD * HD)    // 324

__global__ void k_gate(const float* __restrict__ w1, const float* __restrict__ b1,
                       const float* __restrict__ w2, const float* __restrict__ b2) {
    __shared__ float s_em[EMD * EMD];
    __shared__ float s_h[16 * HPOS];      // [c][pos]
    __shared__ float s_w1[160];           // 144 weights + 16 bias
    __shared__ float s_w2[290];           // 288 weights + 2 bias

    int tid = threadIdx.x;
    if (tid < 144)       s_w1[tid] = w1[tid];
    else if (tid < 160)  s_w1[tid] = b1[tid - 144];
    for (int i = tid; i < 288; i += 256) s_w2[i] = w2[i];
    if (tid < 2) s_w2[288 + tid] = b2[tid];

    int blk = blockIdx.x;
    int b   = blk >> 4;                 // 16 tiles per batch image
    int ty0 = ((blk >> 2) & 3) * TS;
    int tx0 = (blk & 3) * TS;

    // ---- stage 1: em tile with 2-halo, mean computed from partials ----
    for (int i = tid; i < EMD * EMD; i += 256) {
        int iy = i / EMD, ix = i - iy * EMD;
        int gy = ty0 + iy - 2, gx = tx0 + ix - 2;
        float v = 0.f;
        if ((unsigned)gy < (unsigned)Hn && (unsigned)gx < (unsigned)Wn) {
            int p = b * HWn + gy * Wn + gx;
            float s = 0.f;
#pragma unroll
            for (int k = 0; k < SPLIT; ++k)
                s += g_part[k * PIXn + p];
            v = s * (1.0f / (float)Cn);
        }
        s_em[i] = v;
    }
    __syncthreads();

    // ---- stage 2: conv1 + relu at 18x18 positions ----
    for (int i = tid; i < HPOS; i += 256) {
        int iy = i / HD, ix = i - iy * HD;
        int gy = ty0 + iy - 1, gx = tx0 + ix - 1;
        if ((unsigned)gy < (unsigned)Hn && (unsigned)gx < (unsigned)Wn) {
            float patch[9];
#pragma unroll
            for (int dy = 0; dy < 3; ++dy)
#pragma unroll
                for (int dx = 0; dx < 3; ++dx)
                    patch[dy * 3 + dx] = s_em[(iy + dy) * EMD + (ix + dx)];
#pragma unroll
            for (int c = 0; c < 16; ++c) {
                float a = s_w1[144 + c];
#pragma unroll
                for (int k = 0; k < 9; ++k)
                    a = fmaf(s_w1[c * 9 + k], patch[k], a);
                s_h[c * HPOS + i] = fmaxf(a, 0.f);
            }
        } else {
#pragma unroll
            for (int c = 0; c < 16; ++c)
                s_h[c * HPOS + i] = 0.f;     // conv2 SAME padding
        }
    }
    __syncthreads();

    // ---- stage 3: conv2 + sigmoid, one pixel per thread ----
    int iy = tid >> 4, ix = tid & 15;
    float l0 = s_w2[288], l1 = s_w2[289];
#pragma unroll
    for (int ky = 0; ky < 3; ++ky) {
#pragma unroll
        for (int kx = 0; kx < 3; ++kx) {
            int pos = (iy + ky) * HD + (ix + kx);
            int koff = ky * 3 + kx;
#pragma unroll
            for (int c = 0; c < 16; ++c) {
                float hv = s_h[c * HPOS + pos];
                l0 = fmaf(s_w2[c * 9 + koff], hv, l0);
                l1 = fmaf(s_w2[144 + c * 9 + koff], hv, l1);
            }
        }
    }
    g_w0[b * HWn + (ty0 + iy) * Wn + (tx0 + ix)] = 1.0f / (1.0f + expf(l1 - l0));
}

// ---------------------------------------------------------------------------
// k_shift: out = w0 * x[h - sh[g], w] + (1-w0) * x[h, w - sw[g]] (zero-fill)
// Roll of PAD=2 zero-padded tensor + crop == zero-filled shift (|s|<=2).
// Warp holds 2 full rows; w-shift resolved with <=2 warp shuffles.
// ---------------------------------------------------------------------------
__global__ void k_shift(const float* __restrict__ x,
                        const int* __restrict__ shv,
                        const int* __restrict__ swv,
                        float* __restrict__ out) {
    int idx = blockIdx.x * blockDim.x + threadIdx.x;  // < B*C*H*(W/4)
    int wq = idx & 15;
    int h  = (idx >> 4) & 63;
    int t  = idx >> 10;           // b*Cn + c ; uniform across warp
    int b  = t / Cn;
    int c  = t - b * Cn;
    int g  = c >> 6;              // 64 channels per group
    int sh = __ldg(shv + g);
    int sw = __ldg(swv + g);
    int L  = threadIdx.x & 15;    // position within row

    size_t base = (size_t)t * HWn;

    const float4 A = *(const float4*)(x + base + h * Wn + wq * 4);

    int hh = h - sh;
    float4 hv = make_float4(0.f, 0.f, 0.f, 0.f);
    if ((unsigned)hh < (unsigned)Hn)
        hv = *(const float4*)(x + base + hh * Wn + wq * 4);

    float4 wv;
    if (sw == 0) {
        wv = A;
    } else if (sw == 1) {
        float lw = __shfl_up_sync(0xffffffffu, A.w, 1);
        wv = make_float4(L > 0 ? lw : 0.f, A.x, A.y, A.z);
    } else if (sw == 2) {
        float lz = __shfl_up_sync(0xffffffffu, A.z, 1);
        float lw = __shfl_up_sync(0xffffffffu, A.w, 1);
        wv = make_float4(L > 0 ? lz : 0.f, L > 0 ? lw : 0.f, A.x, A.y);
    } else if (sw == -1) {
        float rx = __shfl_down_sync(0xffffffffu, A.x, 1);
        wv = make_float4(A.y, A.z, A.w, L < 15 ? rx : 0.f);
    } else { // sw == -2
        float rx = __shfl_down_sync(0xffffffffu, A.x, 1);
        float ry = __shfl_down_sync(0xffffffffu, A.y, 1);
        wv = make_float4(A.z, A.w, L < 15 ? rx : 0.f, L < 15 ? ry : 0.f);
    }

    float4 wgt = *(const float4*)(g_w0 + b * HWn + h * Wn + wq * 4);

    float4 o;
    o.x = wgt.x * hv.x + (1.f - wgt.x) * wv.x;
    o.y = wgt.y * hv.y + (1.f - wgt.y) * wv.y;
    o.z = wgt.z * hv.z + (1.f - wgt.z) * wv.z;
    o.w = wgt.w * hv.w + (1.f - wgt.w) * wv.w;
    *(float4*)(out + base + h * Wn + wq * 4) = o;
}

// ---------------------------------------------------------------------------
extern "C" void kernel_launch(void* const* d_in, const int* in_sizes, int n_in,
                              void* d_out, int out_size) {
    const float* x   = (const float*)d_in[0];
    const float* eg  = (const float*)d_in[1];
    const float* w1  = (const float*)d_in[2];
    const float* b1  = (const float*)d_in[3];
    const float* w2  = (const float*)d_in[4];
    const float* b2  = (const float*)d_in[5];
    const int*   shv = (const int*)d_in[6];
    const int*   swv = (const int*)d_in[7];
    float* out = (float*)d_out;

    k_mean_part<<<2048, 256>>>(eg);                 // 524288 threads
    k_gate     <<<256, 256>>>(w1, b1, w2, b2);      // 65536 threads
    k_shift    <<<20480, 256>>>(x, shv, swv, out);  // 5,242,880 threads
}

// round 5
// speedup vs baseline: 1.2591x; 1.0086x over previous
#include <cuda_runtime.h>
#include <cstddef>

#define Bn 16
#define Cn 320
#define Hn 64
#define Wn 64
#define HWn 4096          // Hn*Wn
#define PIXn (Bn*HWn)     // 65536 pixels
#define SPLIT 8
#define CPS (Cn / SPLIT)  // 40 channels per split

// Scratch (allocation-free requirement -> __device__ globals)
__device__ __align__(16) float g_part[SPLIT * PIXn]; // partial channel sums
__device__ __align__(16) float g_w0[PIXn];           // softmax weight0 [B,H,W]

// ---------------------------------------------------------------------------
// k1: partial channel sums, 8-way C split, float4 (one thread per 4 pixels).
// 131072 threads x 40 LDG.128 -> deep MLP, low issue pressure.
// ---------------------------------------------------------------------------
__global__ void k_mean_part(const float* __restrict__ eg) {
    int idx = blockIdx.x * blockDim.x + threadIdx.x;  // < SPLIT*PIXn/4 = 131072
    int q = idx & 16383;            // quad index within one split's pixel set
    int s = idx >> 14;              // split
    int b = q >> 10;                // 1024 quads per image plane
    int hw4 = q & 1023;
    const float4* ptr = (const float4*)eg
                      + (size_t)b * Cn * (HWn / 4)
                      + (size_t)s * CPS * (HWn / 4) + hw4;
    float4 a0 = make_float4(0.f, 0.f, 0.f, 0.f), a1 = a0, a2 = a0, a3 = a0;
#pragma unroll
    for (int c = 0; c < CPS; c += 4) {
        float4 v0 = __ldg(ptr + (size_t)(c + 0) * (HWn / 4));
        float4 v1 = __ldg(ptr + (size_t)(c + 1) * (HWn / 4));
        float4 v2 = __ldg(ptr + (size_t)(c + 2) * (HWn / 4));
        float4 v3 = __ldg(ptr + (size_t)(c + 3) * (HWn / 4));
        a0.x += v0.x; a0.y += v0.y; a0.z += v0.z; a0.w += v0.w;
        a1.x += v1.x; a1.y += v1.y; a1.z += v1.z; a1.w += v1.w;
        a2.x += v2.x; a2.y += v2.y; a2.z += v2.z; a2.w += v2.w;
        a3.x += v3.x; a3.y += v3.y; a3.z += v3.z; a3.w += v3.w;
    }
    float4 r;
    r.x = (a0.x + a1.x) + (a2.x + a3.x);
    r.y = (a0.y + a1.y) + (a2.y + a3.y);
    r.z = (a0.z + a1.z) + (a2.z + a3.z);
    r.w = (a0.w + a1.w) + (a2.w + a3.w);
    ((float4*)g_part)[idx] = r;     // same layout: g_part[s*PIXn + p]
}

// ---------------------------------------------------------------------------
// k_gate: fused  mean-finalize -> conv1(1->16)+relu -> conv2(16->2) -> sigmoid
// One block per 16x16 output tile (256 blocks, 256 threads).
// ---------------------------------------------------------------------------
#define TS 16
#define EMD 20            // em tile dim (TS + 2*2 halo)
#define HD 18             // h tile dim  (TS + 2*1 halo)
#define HPOS (HD * HD)    // 324

__global__ void k_gate(const float* __restrict__ w1, const float* __restrict__ b1,
                       const float* __restrict__ w2, const float* __restrict__ b2) {
    __shared__ float s_em[EMD * EMD];
    __shared__ float s_h[16 * HPOS];      // [c][pos]
    __shared__ float s_w1[160];           // 144 weights + 16 bias
    __shared__ float s_w2[290];           // 288 weights + 2 bias

    int tid = threadIdx.x;
    if (tid < 144)       s_w1[tid] = w1[tid];
    else if (tid < 160)  s_w1[tid] = b1[tid - 144];
    for (int i = tid; i < 288; i += 256) s_w2[i] = w2[i];
    if (tid < 2) s_w2[288 + tid] = b2[tid];

    int blk = blockIdx.x;
    int b   = blk >> 4;                 // 16 tiles per batch image
    int ty0 = ((blk >> 2) & 3) * TS;
    int tx0 = (blk & 3) * TS;

    // ---- stage 1: em tile with 2-halo, mean computed from partials ----
    for (int i = tid; i < EMD * EMD; i += 256) {
        int iy = i / EMD, ix = i - iy * EMD;
        int gy = ty0 + iy - 2, gx = tx0 + ix - 2;
        float v = 0.f;
        if ((unsigned)gy < (unsigned)Hn && (unsigned)gx < (unsigned)Wn) {
            int p = b * HWn + gy * Wn + gx;
            float s = 0.f;
#pragma unroll
            for (int k = 0; k < SPLIT; ++k)
                s += g_part[k * PIXn + p];
            v = s * (1.0f / (float)Cn);
        }
        s_em[i] = v;
    }
    __syncthreads();

    // ---- stage 2: conv1 + relu at 18x18 positions ----
    for (int i = tid; i < HPOS; i += 256) {
        int iy = i / HD, ix = i - iy * HD;
        int gy = ty0 + iy - 1, gx = tx0 + ix - 1;
        if ((unsigned)gy < (unsigned)Hn && (unsigned)gx < (unsigned)Wn) {
            float patch[9];
#pragma unroll
            for (int dy = 0; dy < 3; ++dy)
#pragma unroll
                for (int dx = 0; dx < 3; ++dx)
                    patch[dy * 3 + dx] = s_em[(iy + dy) * EMD + (ix + dx)];
#pragma unroll
            for (int c = 0; c < 16; ++c) {
                float a = s_w1[144 + c];
#pragma unroll
                for (int k = 0; k < 9; ++k)
                    a = fmaf(s_w1[c * 9 + k], patch[k], a);
                s_h[c * HPOS + i] = fmaxf(a, 0.f);
            }
        } else {
#pragma unroll
            for (int c = 0; c < 16; ++c)
                s_h[c * HPOS + i] = 0.f;     // conv2 SAME padding
        }
    }
    __syncthreads();

    // ---- stage 3: conv2 + sigmoid, one pixel per thread ----
    int iy = tid >> 4, ix = tid & 15;
    float l0 = s_w2[288], l1 = s_w2[289];
#pragma unroll
    for (int ky = 0; ky < 3; ++ky) {
#pragma unroll
        for (int kx = 0; kx < 3; ++kx) {
            int pos = (iy + ky) * HD + (ix + kx);
            int koff = ky * 3 + kx;
#pragma unroll
            for (int c = 0; c < 16; ++c) {
                float hv = s_h[c * HPOS + pos];
                l0 = fmaf(s_w2[c * 9 + koff], hv, l0);
                l1 = fmaf(s_w2[144 + c * 9 + koff], hv, l1);
            }
        }
    }
    g_w0[b * HWn + (ty0 + iy) * Wn + (tx0 + ix)] = 1.0f / (1.0f + expf(l1 - l0));
}

// ---------------------------------------------------------------------------
// k_shift: out = w0 * x[h - sh[g], w] + (1-w0) * x[h, w - sw[g]] (zero-fill)
// 8 floats (two aligned float4) per thread; 8 threads per 64-float row.
// |sw| <= 2 and warp-uniform -> boundary elements via <=4 pre-shuffles from
// the adjacent lane; row boundary == zero-fill boundary (L==0 / L==7).
// ---------------------------------------------------------------------------
__global__ void k_shift(const float* __restrict__ x,
                        const int* __restrict__ shv,
                        const int* __restrict__ swv,
                        float* __restrict__ out) {
    int idx = blockIdx.x * blockDim.x + threadIdx.x;  // < B*C*H*(W/8) = 2621440
    int seg = idx & 7;            // 8-float segment within row
    int h   = (idx >> 3) & 63;
    int t   = idx >> 9;           // b*Cn + c ; uniform across warp
    int b   = t / Cn;
    int c   = t - b * Cn;
    int g   = c >> 6;             // 64 channels per group
    int sh  = __ldg(shv + g);
    int sw  = __ldg(swv + g);
    int L   = threadIdx.x & 7;    // thread position within row (== seg)

    size_t base = (size_t)t * HWn;
    const float4* rowp = (const float4*)(x + base + h * Wn);
    float4 A0 = rowp[seg * 2];
    float4 A1 = rowp[seg * 2 + 1];
    float a0 = A0.x, a1 = A0.y, a2 = A0.z, a3 = A0.w;
    float a4 = A1.x, a5 = A1.y, a6 = A1.z, a7 = A1.w;

    // h-shifted segment (adjacent row -> L2 hit on the second touch)
    int hh = h - sh;
    float4 h0 = make_float4(0.f, 0.f, 0.f, 0.f), h1 = h0;
    if ((unsigned)hh < (unsigned)Hn) {
        const float4* rp2 = (const float4*)(x + base + hh * Wn);
        h0 = rp2[seg * 2];
        h1 = rp2[seg * 2 + 1];
    }

    // neighbor boundary values for the w-shift
    float pl0 = __shfl_up_sync(0xffffffffu, a6, 1);   // a[-2]
    float pl1 = __shfl_up_sync(0xffffffffu, a7, 1);   // a[-1]
    float nr0 = __shfl_down_sync(0xffffffffu, a0, 1); // a[8]
    float nr1 = __shfl_down_sync(0xffffffffu, a1, 1); // a[9]

    float w0, w1, w2, w3, w4, w5, w6, w7;
    if (sw == 0) {
        w0 = a0; w1 = a1; w2 = a2; w3 = a3; w4 = a4; w5 = a5; w6 = a6; w7 = a7;
    } else if (sw == 1) {
        w0 = (L > 0) ? pl1 : 0.f;
        w1 = a0; w2 = a1; w3 = a2; w4 = a3; w5 = a4; w6 = a5; w7 = a6;
    } else if (sw == 2) {
        w0 = (L > 0) ? pl0 : 0.f;
        w1 = (L > 0) ? pl1 : 0.f;
        w2 = a0; w3 = a1; w4 = a2; w5 = a3; w6 = a4; w7 = a5;
    } else if (sw == -1) {
        w0 = a1; w1 = a2; w2 = a3; w3 = a4; w4 = a5; w5 = a6; w6 = a7;
        w7 = (L < 7) ? nr0 : 0.f;
    } else { // sw == -2
        w0 = a2; w1 = a3; w2 = a4; w3 = a5; w4 = a6; w5 = a7;
        w6 = (L < 7) ? nr0 : 0.f;
        w7 = (L < 7) ? nr1 : 0.f;
    }

    const float4* wp = (const float4*)(g_w0 + b * HWn + h * Wn) + seg * 2;
    float4 g0 = wp[0], g1 = wp[1];

    float4 o0, o1;
    o0.x = g0.x * h0.x + (1.f - g0.x) * w0;
    o0.y = g0.y * h0.y + (1.f - g0.y) * w1;
    o0.z = g0.z * h0.z + (1.f - g0.z) * w2;
    o0.w = g0.w * h0.w + (1.f - g0.w) * w3;
    o1.x = g1.x * h1.x + (1.f - g1.x) * w4;
    o1.y = g1.y * h1.y + (1.f - g1.y) * w5;
    o1.z = g1.z * h1.z + (1.f - g1.z) * w6;
    o1.w = g1.w * h1.w + (1.f - g1.w) * w7;

    float4* op = (float4*)(out + base + h * Wn) + seg * 2;
    op[0] = o0;
    op[1] = o1;
}

// ---------------------------------------------------------------------------
extern "C" void kernel_launch(void* const* d_in, const int* in_sizes, int n_in,
                              void* d_out, int out_size) {
    const float* x   = (const float*)d_in[0];
    const float* eg  = (const float*)d_in[1];
    const float* w1  = (const float*)d_in[2];
    const float* b1  = (const float*)d_in[3];
    const float* w2  = (const float*)d_in[4];
    const float* b2  = (const float*)d_in[5];
    const int*   shv = (const int*)d_in[6];
    const int*   swv = (const int*)d_in[7];
    float* out = (float*)d_out;

    k_mean_part<<<512, 256>>>(eg);                  // 131072 threads
    k_gate     <<<256, 256>>>(w1, b1, w2, b2);      // 65536 threads
    k_shift    <<<10240, 256>>>(x, shv, swv, out);  // 2,621,440 threads
}

// round 7
// speedup vs baseline: 1.2870x; 1.0222x over previous
#include <cuda_runtime.h>
#include <cstddef>

#define Bn 16
#define Cn 320
#define Hn 64
#define Wn 64
#define HWn 4096          // Hn*Wn
#define PIXn (Bn*HWn)     // 65536 pixels
#define SPLIT 16
#define CPS (Cn / SPLIT)  // 20 channels per split

// Scratch (allocation-free requirement -> __device__ globals)
__device__ __align__(16) float g_part[SPLIT * PIXn]; // partial channel sums (4MB)
__device__ __align__(16) float g_w0[PIXn];           // softmax weight0 [B,H,W]

// ---------------------------------------------------------------------------
// k1: partial channel sums, 16-way C split, float4 (one thread per 4 pixels).
// 262144 threads -> ~55 warps/SM -> deep chip-wide MLP for the strided reads.
// ---------------------------------------------------------------------------
__global__ void __launch_bounds__(256) k_mean_part(const float* __restrict__ eg) {
    int idx = blockIdx.x * blockDim.x + threadIdx.x;  // < SPLIT*PIXn/4 = 262144
    int q = idx & 16383;            // quad index within one split's pixel set
    int s = idx >> 14;              // split 0..15
    int b = q >> 10;                // 1024 quads per image plane
    int hw4 = q & 1023;
    const float4* ptr = (const float4*)eg
                      + (size_t)b * Cn * (HWn / 4)
                      + (size_t)s * CPS * (HWn / 4) + hw4;
    float4 a0 = make_float4(0.f, 0.f, 0.f, 0.f), a1 = a0, a2 = a0, a3 = a0;
#pragma unroll
    for (int c = 0; c < CPS; c += 4) {
        float4 v0 = __ldg(ptr + (size_t)(c + 0) * (HWn / 4));
        float4 v1 = __ldg(ptr + (size_t)(c + 1) * (HWn / 4));
        float4 v2 = __ldg(ptr + (size_t)(c + 2) * (HWn / 4));
        float4 v3 = __ldg(ptr + (size_t)(c + 3) * (HWn / 4));
        a0.x += v0.x; a0.y += v0.y; a0.z += v0.z; a0.w += v0.w;
        a1.x += v1.x; a1.y += v1.y; a1.z += v1.z; a1.w += v1.w;
        a2.x += v2.x; a2.y += v2.y; a2.z += v2.z; a2.w += v2.w;
        a3.x += v3.x; a3.y += v3.y; a3.z += v3.z; a3.w += v3.w;
    }
    float4 r;
    r.x = (a0.x + a1.x) + (a2.x + a3.x);
    r.y = (a0.y + a1.y) + (a2.y + a3.y);
    r.z = (a0.z + a1.z) + (a2.z + a3.z);
    r.w = (a0.w + a1.w) + (a2.w + a3.w);
    ((float4*)g_part)[idx] = r;     // layout: g_part[s*PIXn + p]
}

// ---------------------------------------------------------------------------
// k_gate: fused  mean-finalize -> conv1(1->16)+relu -> conv2(16->2) -> sigmoid
// One block per 16x16 output tile (256 blocks, 256 threads).
// ---------------------------------------------------------------------------
#define TS 16
#define EMD 20            // em tile dim (TS + 2*2 halo)
#define HD 18             // h tile dim  (TS + 2*1 halo)
#define HPOS (HD * HD)    // 324

__global__ void k_gate(const float* __restrict__ w1, const float* __restrict__ b1,
                       const float* __restrict__ w2, const float* __restrict__ b2) {
    __shared__ float s_em[EMD * EMD];
    __shared__ float s_h[16 * HPOS];      // [c][pos]
    __shared__ float s_w1[160];           // 144 weights + 16 bias
    __shared__ float s_w2[290];           // 288 weights + 2 bias

    int tid = threadIdx.x;
    if (tid < 144)       s_w1[tid] = w1[tid];
    else if (tid < 160)  s_w1[tid] = b1[tid - 144];
    for (int i = tid; i < 288; i += 256) s_w2[i] = w2[i];
    if (tid < 2) s_w2[288 + tid] = b2[tid];

    int blk = blockIdx.x;
    int b   = blk >> 4;                 // 16 tiles per batch image
    int ty0 = ((blk >> 2) & 3) * TS;
    int tx0 = (blk & 3) * TS;

    // ---- stage 1: em tile with 2-halo, mean computed from partials ----
    for (int i = tid; i < EMD * EMD; i += 256) {
        int iy = i / EMD, ix = i - iy * EMD;
        int gy = ty0 + iy - 2, gx = tx0 + ix - 2;
        float v = 0.f;
        if ((unsigned)gy < (unsigned)Hn && (unsigned)gx < (unsigned)Wn) {
            int p = b * HWn + gy * Wn + gx;
            float s = 0.f;
#pragma unroll
            for (int k = 0; k < SPLIT; ++k)
                s += g_part[k * PIXn + p];
            v = s * (1.0f / (float)Cn);
        }
        s_em[i] = v;
    }
    __syncthreads();

    // ---- stage 2: conv1 + relu at 18x18 positions ----
    for (int i = tid; i < HPOS; i += 256) {
        int iy = i / HD, ix = i - iy * HD;
        int gy = ty0 + iy - 1, gx = tx0 + ix - 1;
        if ((unsigned)gy < (unsigned)Hn && (unsigned)gx < (unsigned)Wn) {
            float patch[9];
#pragma unroll
            for (int dy = 0; dy < 3; ++dy)
#pragma unroll
                for (int dx = 0; dx < 3; ++dx)
                    patch[dy * 3 + dx] = s_em[(iy + dy) * EMD + (ix + dx)];
#pragma unroll
            for (int c = 0; c < 16; ++c) {
                float a = s_w1[144 + c];
#pragma unroll
                for (int k = 0; k < 9; ++k)
                    a = fmaf(s_w1[c * 9 + k], patch[k], a);
                s_h[c * HPOS + i] = fmaxf(a, 0.f);
            }
        } else {
#pragma unroll
            for (int c = 0; c < 16; ++c)
                s_h[c * HPOS + i] = 0.f;     // conv2 SAME padding
        }
    }
    __syncthreads();

    // ---- stage 3: conv2 + sigmoid, one pixel per thread ----
    int iy = tid >> 4, ix = tid & 15;
    float l0 = s_w2[288], l1 = s_w2[289];
#pragma unroll
    for (int ky = 0; ky < 3; ++ky) {
#pragma unroll
        for (int kx = 0; kx < 3; ++kx) {
            int pos = (iy + ky) * HD + (ix + kx);
            int koff = ky * 3 + kx;
#pragma unroll
            for (int c = 0; c < 16; ++c) {
                float hv = s_h[c * HPOS + pos];
                l0 = fmaf(s_w2[c * 9 + koff], hv, l0);
                l1 = fmaf(s_w2[144 + c * 9 + koff], hv, l1);
            }
        }
    }
    g_w0[b * HWn + (ty0 + iy) * Wn + (tx0 + ix)] = 1.0f / (1.0f + expf(l1 - l0));
}

// ---------------------------------------------------------------------------
// k_shift: out = w0 * x[h - sh[g], w] + (1-w0) * x[h, w - sw[g]] (zero-fill)
// 8 floats (two aligned float4) per thread; 8 threads per 64-float row.
// Branchless: the h-shifted row load is clamped to a valid row and masked,
// so all 6 float4 loads issue unconditionally and batch at the top.
// w-shift resolved via warp shuffles (|sw|<=2, warp-uniform).
// ---------------------------------------------------------------------------
__global__ void __launch_bounds__(256) k_shift(const float* __restrict__ x,
                        const int* __restrict__ shv,
                        const int* __restrict__ swv,
                        float* __restrict__ out) {
    int idx = blockIdx.x * blockDim.x + threadIdx.x;  // < B*C*H*(W/8) = 2621440
    int seg = idx & 7;            // 8-float segment within row
    int h   = (idx >> 3) & 63;
    int t   = idx >> 9;           // b*Cn + c ; uniform across warp
    int b   = t / Cn;
    int c   = t - b * Cn;
    int g   = c >> 6;             // 64 channels per group
    int sh  = __ldg(shv + g);
    int sw  = __ldg(swv + g);
    int L   = threadIdx.x & 7;    // thread position within row (== seg)

    size_t base = (size_t)t * HWn;

    int hh = h - sh;
    bool hok = (unsigned)hh < (unsigned)Hn;
    int hc = hok ? hh : h;        // safe row (masked below)
    float m = hok ? 1.f : 0.f;

    // issue all global loads up front
    const float4* rowp = (const float4*)(x + base + h * Wn) + seg * 2;
    const float4* rp2  = (const float4*)(x + base + hc * Wn) + seg * 2;
    const float4* wp   = (const float4*)(g_w0 + b * HWn + h * Wn) + seg * 2;
    float4 A0 = rowp[0];
    float4 A1 = rowp[1];
    float4 h0 = rp2[0];
    float4 h1 = rp2[1];
    float4 g0 = wp[0];
    float4 g1 = wp[1];

    float a0 = A0.x, a1 = A0.y, a2 = A0.z, a3 = A0.w;
    float a4 = A1.x, a5 = A1.y, a6 = A1.z, a7 = A1.w;

    // neighbor boundary values for the w-shift
    float pl0 = __shfl_up_sync(0xffffffffu, a6, 1);   // a[-2]
    float pl1 = __shfl_up_sync(0xffffffffu, a7, 1);   // a[-1]
    float nr0 = __shfl_down_sync(0xffffffffu, a0, 1); // a[8]
    float nr1 = __shfl_down_sync(0xffffffffu, a1, 1); // a[9]

    float w0, w1, w2, w3, w4, w5, w6, w7;
    if (sw == 0) {
        w0 = a0; w1 = a1; w2 = a2; w3 = a3; w4 = a4; w5 = a5; w6 = a6; w7 = a7;
    } else if (sw == 1) {
        w0 = (L > 0) ? pl1 : 0.f;
        w1 = a0; w2 = a1; w3 = a2; w4 = a3; w5 = a4; w6 = a5; w7 = a6;
    } else if (sw == 2) {
        w0 = (L > 0) ? pl0 : 0.f;
        w1 = (L > 0) ? pl1 : 0.f;
        w2 = a0; w3 = a1; w4 = a2; w5 = a3; w6 = a4; w7 = a5;
    } else if (sw == -1) {
        w0 = a1; w1 = a2; w2 = a3; w3 = a4; w4 = a5; w5 = a6; w6 = a7;
        w7 = (L < 7) ? nr0 : 0.f;
    } else { // sw == -2
        w0 = a2; w1 = a3; w2 = a4; w3 = a5; w4 = a6; w5 = a7;
        w6 = (L < 7) ? nr0 : 0.f;
        w7 = (L < 7) ? nr1 : 0.f;
    }

    float4 o0, o1;
    o0.x = g0.x * (m * h0.x) + (1.f - g0.x) * w0;
    o0.y = g0.y * (m * h0.y) + (1.f - g0.y) * w1;
    o0.z = g0.z * (m * h0.z) + (1.f - g0.z) * w2;
    o0.w = g0.w * (m * h0.w) + (1.f - g0.w) * w3;
    o1.x = g1.x * (m * h1.x) + (1.f - g1.x) * w4;
    o1.y = g1.y * (m * h1.y) + (1.f - g1.y) * w5;
    o1.z = g1.z * (m * h1.z) + (1.f - g1.z) * w6;
    o1.w = g1.w * (m * h1.w) + (1.f - g1.w) * w7;

    float4* op = (float4*)(out + base + h * Wn) + seg * 2;
    __stcs(op,     o0);   // streaming store: out never re-read
    __stcs(op + 1, o1);
}

// ---------------------------------------------------------------------------
extern "C" void kernel_launch(void* const* d_in, const int* in_sizes, int n_in,
                              void* d_out, int out_size) {
    const float* x   = (const float*)d_in[0];
    const float* eg  = (const float*)d_in[1];
    const float* w1  = (const float*)d_in[2];
    const float* b1  = (const float*)d_in[3];
    const float* w2  = (const float*)d_in[4];
    const float* b2  = (const float*)d_in[5];
    const int*   shv = (const int*)d_in[6];
    const int*   swv = (const int*)d_in[7];
    float* out = (float*)d_out;

    k_mean_part<<<1024, 256>>>(eg);                 // 262144 threads
    k_gate     <<<256, 256>>>(w1, b1, w2, b2);      // 65536 threads
    k_shift    <<<10240, 256>>>(x, shv, swv, out);  // 2,621,440 threads
}

// round 8
// speedup vs baseline: 1.3452x; 1.0452x over previous
#include <cuda_runtime.h>
#include <cstddef>

#define Bn 16
#define Cn 320
#define Hn 64
#define Wn 64
#define HWn 4096          // Hn*Wn
#define PIXn (Bn*HWn)     // 65536 pixels
#define SPLIT 8
#define CPS (Cn / SPLIT)  // 40 channels per split

// Scratch (allocation-free requirement -> __device__ globals)
__device__ __align__(16) float g_part[SPLIT * PIXn]; // partial channel sums (2MB)
__device__ __align__(16) float g_w0[PIXn];           // softmax weight0 [B,H,W]

// ---------------------------------------------------------------------------
// k1: partial channel sums, 8-way C split, float4 (one thread per 4 pixels).
// Empirically the best mean config (R5: 17.0us, 5.08TB/s). eg is a pure
// stream (zero reuse) -> __ldcs keeps it from evicting L2 lines that the
// later kernels want (x rows, w0, partials).
// ---------------------------------------------------------------------------
__global__ void __launch_bounds__(256) k_mean_part(const float* __restrict__ eg) {
    int idx = blockIdx.x * blockDim.x + threadIdx.x;  // < SPLIT*PIXn/4 = 131072
    int q = idx & 16383;            // quad index within one split's pixel set
    int s = idx >> 14;              // split 0..7
    int b = q >> 10;                // 1024 quads per image plane
    int hw4 = q & 1023;
    const float4* ptr = (const float4*)eg
                      + (size_t)b * Cn * (HWn / 4)
                      + (size_t)s * CPS * (HWn / 4) + hw4;
    float4 a0 = make_float4(0.f, 0.f, 0.f, 0.f), a1 = a0, a2 = a0, a3 = a0;
#pragma unroll
    for (int c = 0; c < CPS; c += 4) {
        float4 v0 = __ldcs(ptr + (size_t)(c + 0) * (HWn / 4));
        float4 v1 = __ldcs(ptr + (size_t)(c + 1) * (HWn / 4));
        float4 v2 = __ldcs(ptr + (size_t)(c + 2) * (HWn / 4));
        float4 v3 = __ldcs(ptr + (size_t)(c + 3) * (HWn / 4));
        a0.x += v0.x; a0.y += v0.y; a0.z += v0.z; a0.w += v0.w;
        a1.x += v1.x; a1.y += v1.y; a1.z += v1.z; a1.w += v1.w;
        a2.x += v2.x; a2.y += v2.y; a2.z += v2.z; a2.w += v2.w;
        a3.x += v3.x; a3.y += v3.y; a3.z += v3.z; a3.w += v3.w;
    }
    float4 r;
    r.x = (a0.x + a1.x) + (a2.x + a3.x);
    r.y = (a0.y + a1.y) + (a2.y + a3.y);
    r.z = (a0.z + a1.z) + (a2.z + a3.z);
    r.w = (a0.w + a1.w) + (a2.w + a3.w);
    ((float4*)g_part)[idx] = r;     // layout: g_part[s*PIXn + p]
}

// ---------------------------------------------------------------------------
// k_gate: fused  mean-finalize -> conv1(1->16)+relu -> conv2(16->2) -> sigmoid
// One block per 16x16 output tile (256 blocks, 256 threads).
// ---------------------------------------------------------------------------
#define TS 16
#define EMD 20            // em tile dim (TS + 2*2 halo)
#define HD 18             // h tile dim  (TS + 2*1 halo)
#define HPOS (HD * HD)    // 324

__global__ void k_gate(const float* __restrict__ w1, const float* __restrict__ b1,
                       const float* __restrict__ w2, const float* __restrict__ b2) {
    __shared__ float s_em[EMD * EMD];
    __shared__ float s_h[16 * HPOS];      // [c][pos]
    __shared__ float s_w1[160];           // 144 weights + 16 bias
    __shared__ float s_w2[290];           // 288 weights + 2 bias

    int tid = threadIdx.x;
    if (tid < 144)       s_w1[tid] = w1[tid];
    else if (tid < 160)  s_w1[tid] = b1[tid - 144];
    for (int i = tid; i < 288; i += 256) s_w2[i] = w2[i];
    if (tid < 2) s_w2[288 + tid] = b2[tid];

    int blk = blockIdx.x;
    int b   = blk >> 4;                 // 16 tiles per batch image
    int ty0 = ((blk >> 2) & 3) * TS;
    int tx0 = (blk & 3) * TS;

    // ---- stage 1: em tile with 2-halo, mean computed from partials ----
    for (int i = tid; i < EMD * EMD; i += 256) {
        int iy = i / EMD, ix = i - iy * EMD;
        int gy = ty0 + iy - 2, gx = tx0 + ix - 2;
        float v = 0.f;
        if ((unsigned)gy < (unsigned)Hn && (unsigned)gx < (unsigned)Wn) {
            int p = b * HWn + gy * Wn + gx;
            float s = 0.f;
#pragma unroll
            for (int k = 0; k < SPLIT; ++k)
                s += g_part[k * PIXn + p];
            v = s * (1.0f / (float)Cn);
        }
        s_em[i] = v;
    }
    __syncthreads();

    // ---- stage 2: conv1 + relu at 18x18 positions ----
    for (int i = tid; i < HPOS; i += 256) {
        int iy = i / HD, ix = i - iy * HD;
        int gy = ty0 + iy - 1, gx = tx0 + ix - 1;
        if ((unsigned)gy < (unsigned)Hn && (unsigned)gx < (unsigned)Wn) {
            float patch[9];
#pragma unroll
            for (int dy = 0; dy < 3; ++dy)
#pragma unroll
                for (int dx = 0; dx < 3; ++dx)
                    patch[dy * 3 + dx] = s_em[(iy + dy) * EMD + (ix + dx)];
#pragma unroll
            for (int c = 0; c < 16; ++c) {
                float a = s_w1[144 + c];
#pragma unroll
                for (int k = 0; k < 9; ++k)
                    a = fmaf(s_w1[c * 9 + k], patch[k], a);
                s_h[c * HPOS + i] = fmaxf(a, 0.f);
            }
        } else {
#pragma unroll
            for (int c = 0; c < 16; ++c)
                s_h[c * HPOS + i] = 0.f;     // conv2 SAME padding
        }
    }
    __syncthreads();

    // ---- stage 3: conv2 + sigmoid, one pixel per thread ----
    int iy = tid >> 4, ix = tid & 15;
    float l0 = s_w2[288], l1 = s_w2[289];
#pragma unroll
    for (int ky = 0; ky < 3; ++ky) {
#pragma unroll
        for (int kx = 0; kx < 3; ++kx) {
            int pos = (iy + ky) * HD + (ix + kx);
            int koff = ky * 3 + kx;
#pragma unroll
            for (int c = 0; c < 16; ++c) {
                float hv = s_h[c * HPOS + pos];
                l0 = fmaf(s_w2[c * 9 + koff], hv, l0);
                l1 = fmaf(s_w2[144 + c * 9 + koff], hv, l1);
            }
        }
    }
    g_w0[b * HWn + (ty0 + iy) * Wn + (tx0 + ix)] = 1.0f / (1.0f + expf(l1 - l0));
}

// ---------------------------------------------------------------------------
// k_shift: out = w0 * x[h - sh[g], w] + (1-w0) * x[h, w - sw[g]] (zero-fill)
// 8 floats (two aligned float4) per thread; 8 threads per 64-float row.
// Branchless h-load (clamped + masked) so all 6 float4 loads batch at the
// top; w-shift via warp shuffles; streaming stores.
// ---------------------------------------------------------------------------
__global__ void __launch_bounds__(256) k_shift(const float* __restrict__ x,
                        const int* __restrict__ shv,
                        const int* __restrict__ swv,
                        float* __restrict__ out) {
    int idx = blockIdx.x * blockDim.x + threadIdx.x;  // < B*C*H*(W/8) = 2621440
    int seg = idx & 7;            // 8-float segment within row
    int h   = (idx >> 3) & 63;
    int t   = idx >> 9;           // b*Cn + c ; uniform across warp
    int b   = t / Cn;
    int c   = t - b * Cn;
    int g   = c >> 6;             // 64 channels per group
    int sh  = __ldg(shv + g);
    int sw  = __ldg(swv + g);
    int L   = threadIdx.x & 7;    // thread position within row (== seg)

    size_t base = (size_t)t * HWn;

    int hh = h - sh;
    bool hok = (unsigned)hh < (unsigned)Hn;
    int hc = hok ? hh : h;        // safe row (masked below)
    float m = hok ? 1.f : 0.f;

    // issue all global loads up front
    const float4* rowp = (const float4*)(x + base + h * Wn) + seg * 2;
    const float4* rp2  = (const float4*)(x + base + hc * Wn) + seg * 2;
    const float4* wp   = (const float4*)(g_w0 + b * HWn + h * Wn) + seg * 2;
    float4 A0 = rowp[0];
    float4 A1 = rowp[1];
    float4 h0 = rp2[0];
    float4 h1 = rp2[1];
    float4 g0 = wp[0];
    float4 g1 = wp[1];

    float a0 = A0.x, a1 = A0.y, a2 = A0.z, a3 = A0.w;
    float a4 = A1.x, a5 = A1.y, a6 = A1.z, a7 = A1.w;

    // neighbor boundary values for the w-shift
    float pl0 = __shfl_up_sync(0xffffffffu, a6, 1);   // a[-2]
    float pl1 = __shfl_up_sync(0xffffffffu, a7, 1);   // a[-1]
    float nr0 = __shfl_down_sync(0xffffffffu, a0, 1); // a[8]
    float nr1 = __shfl_down_sync(0xffffffffu, a1, 1); // a[9]

    float w0, w1, w2, w3, w4, w5, w6, w7;
    if (sw == 0) {
        w0 = a0; w1 = a1; w2 = a2; w3 = a3; w4 = a4; w5 = a5; w6 = a6; w7 = a7;
    } else if (sw == 1) {
        w0 = (L > 0) ? pl1 : 0.f;
        w1 = a0; w2 = a1; w3 = a2; w4 = a3; w5 = a4; w6 = a5; w7 = a6;
    } else if (sw == 2) {
        w0 = (L > 0) ? pl0 : 0.f;
        w1 = (L > 0) ? pl1 : 0.f;
        w2 = a0; w3 = a1; w4 = a2; w5 = a3; w6 = a4; w7 = a5;
    } else if (sw == -1) {
        w0 = a1; w1 = a2; w2 = a3; w3 = a4; w4 = a5; w5 = a6; w6 = a7;
        w7 = (L < 7) ? nr0 : 0.f;
    } else { // sw == -2
        w0 = a2; w1 = a3; w2 = a4; w3 = a5; w4 = a6; w5 = a7;
        w6 = (L < 7) ? nr0 : 0.f;
        w7 = (L < 7) ? nr1 : 0.f;
    }

    float4 o0, o1;
    o0.x = g0.x * (m * h0.x) + (1.f - g0.x) * w0;
    o0.y = g0.y * (m * h0.y) + (1.f - g0.y) * w1;
    o0.z = g0.z * (m * h0.z) + (1.f - g0.z) * w2;
    o0.w = g0.w * (m * h0.w) + (1.f - g0.w) * w3;
    o1.x = g1.x * (m * h1.x) + (1.f - g1.x) * w4;
    o1.y = g1.y * (m * h1.y) + (1.f - g1.y) * w5;
    o1.z = g1.z * (m * h1.z) + (1.f - g1.z) * w6;
    o1.w = g1.w * (m * h1.w) + (1.f - g1.w) * w7;

    float4* op = (float4*)(out + base + h * Wn) + seg * 2;
    __stcs(op,     o0);   // streaming store: out never re-read
    __stcs(op + 1, o1);
}

// ---------------------------------------------------------------------------
extern "C" void kernel_launch(void* const* d_in, const int* in_sizes, int n_in,
                              void* d_out, int out_size) {
    const float* x   = (const float*)d_in[0];
    const float* eg  = (const float*)d_in[1];
    const float* w1  = (const float*)d_in[2];
    const float* b1  = (const float*)d_in[3];
    const float* w2  = (const float*)d_in[4];
    const float* b2  = (const float*)d_in[5];
    const int*   shv = (const int*)d_in[6];
    const int*   swv = (const int*)d_in[7];
    float* out = (float*)d_out;

    k_mean_part<<<512, 256>>>(eg);                  // 131072 threads
    k_gate     <<<256, 256>>>(w1, b1, w2, b2);      // 65536 threads
    k_shift    <<<10240, 256>>>(x, shv, swv, out);  // 2,621,440 threads
}